// round 16
// baseline (speedup 1.0000x reference)
#include <cuda_runtime.h>

#define T_SEQ   2048
#define BATCH   64
#define INP     16
#define HEADS   8
#define HID     64
#define GATES   256
#define BC      2
#define NTHREADS 512
#define OUT_ELEMS  (T_SEQ * BATCH * HEADS)
#define LOUT_ELEMS (T_SEQ * BATCH * HID)

// Packed fp32x2 FMA (sm_100+): 2 MACs/instr, 2x FFMA throughput.
__device__ __forceinline__ float2 ffma2(float2 a, float2 b, float2 c) {
    float2 d;
    asm("fma.rn.f32x2 %0, %1, %2, %3;"
        : "=l"(reinterpret_cast<unsigned long long&>(d))
        : "l"(reinterpret_cast<const unsigned long long&>(a)),
          "l"(reinterpret_cast<const unsigned long long&>(b)),
          "l"(reinterpret_cast<const unsigned long long&>(c)));
    return d;
}

__device__ __forceinline__ float fsig(float x) {
    return __fdividef(1.0f, 1.0f + __expf(-x));
}
__device__ __forceinline__ float ftanh_(float x) {
    return fmaf(2.0f, fsig(2.0f * x), -1.0f);
}

// CTA = (head, 2 batches), 512 threads, occ 2 (k-split halves regs + chains).
//
// Thread = (gate row, k-half):
//   warp w (0..15) owns rows [16w, 16w+16); lane l: rl = l&15, kh = l>>4
//   row = 16w + rl; row's gate = w>>2 (warp-uniform activation branch).
// Step:
//   phase 1: half-k partial z for both batches (40 ffma2), ONE shfl_xor(16)
//            per batch combines the halves; lane-half kh activates batch kh's
//            gate and stores it to its zb bank (banks 272 floats apart ->
//            conflict-free STS). Barrier.
//   phase 2: threads 0..127 = (b,d): c/h update (single tanh chain), store h
//            to double-buffered hs. Threads 128..255 drain step t-1's lout/out
//            via fire-and-forget REDs from the still-live hs[t&1]. Barrier.
__global__ void __launch_bounds__(NTHREADS, 2)
lstm_kernel(const float* __restrict__ x,    const float* __restrict__ Wih,
            const float* __restrict__ Whh,  const float* __restrict__ bih,
            const float* __restrict__ bhh,  const float* __restrict__ Wlin,
            const float* __restrict__ blin, float* __restrict__ out,
            float* __restrict__ lout)
{
    const int h    = blockIdx.x >> 5;          // head 0..7
    const int b0   = (blockIdx.x & 31) * BC;   // first batch of this CTA
    const int tid  = threadIdx.x;
    const int w    = tid >> 5;                 // warp 0..15
    const int l    = tid & 31;
    const int rl   = l & 15;
    const int kh   = l >> 4;                   // k-half 0/1
    const int row  = w * 16 + rl;              // gate row 0..255
    const int gate = w >> 2;                   // 0:i 1:f 2:g 3:o (warp-uniform)

    __shared__ __align__(16) float hs[2][BC * HID];  // [buf][b*64+d]
    __shared__ __align__(16) float xs[2][BC * INP];  // x double buffer
    __shared__ __align__(16) float zb[272 + GATES];  // bank0 @0, bank1 @272

    // ---- weights -> registers (row, k-half) ----
    float2 w2[16];                              // 32 of 64 Whh-k
    {
        const float4* wr = reinterpret_cast<const float4*>(
            Whh + (size_t)(h * GATES + row) * HID + kh * 32);
#pragma unroll
        for (int q = 0; q < 8; ++q) {
            float4 v = wr[q];
            w2[2 * q]     = make_float2(v.x, v.y);
            w2[2 * q + 1] = make_float2(v.z, v.w);
        }
    }
    float2 wi2[4];                              // 8 of 16 Wih-k
    {
        const float4* wr = reinterpret_cast<const float4*>(
            Wih + (size_t)(h * GATES + row) * INP + kh * 8);
#pragma unroll
        for (int q = 0; q < 2; ++q) {
            float4 v = wr[q];
            wi2[2 * q]     = make_float2(v.x, v.y);
            wi2[2 * q + 1] = make_float2(v.z, v.w);
        }
    }
    const float bias = (kh == 0) ? (bih[h * GATES + row] + bhh[h * GATES + row]) : 0.0f;
    // phase-2 / drain constants (indexed by this thread's (b,d) role)
    const int   d2       = tid & 63;
    const float wlin_d   = Wlin[h * HID + d2];
    const float blin_add = (d2 == 0) ? blin[h] : 0.0f;

    // ---- init ----
    if (tid < BC * HID) hs[0][tid] = 0.0f;
    float c = 0.0f;                             // live only in tid<128
    float xreg = 0.0f;
    if (tid < BC * INP) {
        xs[0][tid] = x[(size_t)0 * BATCH * INP + b0 * INP + tid];
        xreg       = x[(size_t)1 * BATCH * INP + b0 * INP + tid];
    }
    __syncthreads();

    for (int t = 0; t < T_SEQ; ++t) {
        const float* hb = hs[t & 1];
        const float* xb = xs[t & 1];

        // ---- phase 1: half-k partial z, both batches ----
        float z0, z1;
        {
            float2 a0 = make_float2(bias, 0.0f), a1 = make_float2(0.0f, 0.0f);
            float2 c0 = make_float2(bias, 0.0f), c1 = make_float2(0.0f, 0.0f);
            const float4* hv0 = reinterpret_cast<const float4*>(hb + kh * 32);
            const float4* hv1 = reinterpret_cast<const float4*>(hb + HID + kh * 32);
#pragma unroll
            for (int q = 0; q < 8; ++q) {
                float4 v0 = hv0[q], v1 = hv1[q];
                a0 = ffma2(w2[2 * q],     make_float2(v0.x, v0.y), a0);
                a1 = ffma2(w2[2 * q + 1], make_float2(v0.z, v0.w), a1);
                c0 = ffma2(w2[2 * q],     make_float2(v1.x, v1.y), c0);
                c1 = ffma2(w2[2 * q + 1], make_float2(v1.z, v1.w), c1);
            }
            const float4* xv0 = reinterpret_cast<const float4*>(xb + kh * 8);
            const float4* xv1 = reinterpret_cast<const float4*>(xb + INP + kh * 8);
#pragma unroll
            for (int q = 0; q < 2; ++q) {
                float4 v0 = xv0[q], v1 = xv1[q];
                a0 = ffma2(wi2[2 * q],     make_float2(v0.x, v0.y), a0);
                a1 = ffma2(wi2[2 * q + 1], make_float2(v0.z, v0.w), a1);
                c0 = ffma2(wi2[2 * q],     make_float2(v1.x, v1.y), c0);
                c1 = ffma2(wi2[2 * q + 1], make_float2(v1.z, v1.w), c1);
            }
            z0 = (a0.x + a0.y) + (a1.x + a1.y);
            z1 = (c0.x + c0.y) + (c1.x + c1.y);
        }
        // combine k-halves (one shfl per batch; both halves get full sums)
        z0 += __shfl_xor_sync(0xffffffffu, z0, 16);
        z1 += __shfl_xor_sync(0xffffffffu, z1, 16);

        // lane-half kh activates batch kh only (halves MUFU work)
        float zmine = kh ? z1 : z0;
        float za = (gate == 2) ? ftanh_(zmine) : fsig(zmine);
        zb[kh * 272 + row] = za;
        __syncthreads();

        // ---- phase 2 ----
        if (tid < BC * HID) {                   // (b,d) = (tid>>6, tid&63)
            const float* zsrc = zb + (tid >> 6) * 272;
            float si = zsrc[0 * HID + d2];
            float sf = zsrc[1 * HID + d2];
            float tg = zsrc[2 * HID + d2];
            float so = zsrc[3 * HID + d2];
            c = fmaf(sf, c, si * tg);
            hs[(t + 1) & 1][tid] = so * ftanh_(c);
        } else if (tid < 2 * BC * HID && t > 0) {
            // drain step t-1 outputs from hs[t&1] = h_{t-1}
            const int idx = tid - BC * HID;     // (b,d) = (idx>>6, d2)
            float hp = hb[idx];
            atomicAdd(lout + (size_t)((t - 1) * BATCH + b0 + (idx >> 6)) * HID + d2, hp);
            atomicAdd(out  + (size_t)((t - 1) * BATCH + b0 + (idx >> 6)) * HEADS + h,
                      fmaf(hp, wlin_d, blin_add));
        }

        // x pipeline: publish x_{t+1} (loaded a step ago), prefetch x_{t+2}
        if (tid < BC * INP) {
            if (t + 1 < T_SEQ) xs[(t + 1) & 1][tid] = xreg;
            if (t + 2 < T_SEQ) xreg = x[(size_t)(t + 2) * BATCH * INP + b0 * INP + tid];
        }
        __syncthreads();
    }

    // drain final step: h_{T-1} lives in hs[T_SEQ & 1] = hs[0]
    if (tid >= BC * HID && tid < 2 * BC * HID) {
        const int idx = tid - BC * HID;
        float hp = hs[T_SEQ & 1][idx];
        atomicAdd(lout + (size_t)((T_SEQ - 1) * BATCH + b0 + (idx >> 6)) * HID + d2, hp);
        atomicAdd(out  + (size_t)((T_SEQ - 1) * BATCH + b0 + (idx >> 6)) * HEADS + h,
                  fmaf(hp, wlin_d, blin_add));
    }
}

extern "C" void kernel_launch(void* const* d_in, const int* in_sizes, int n_in,
                              void* d_out, int out_size) {
    const float* x    = (const float*)d_in[0];
    const float* Wih  = (const float*)d_in[1];
    const float* Whh  = (const float*)d_in[2];
    const float* bih  = (const float*)d_in[3];
    const float* bhh  = (const float*)d_in[4];
    const float* Wlin = (const float*)d_in[5];
    const float* blin = (const float*)d_in[6];

    float* out  = (float*)d_out;                 // (T,B,H), atomic-accumulated
    float* lout = out + OUT_ELEMS;               // (T,B,HID), atomic-accumulated

    // both regions are accumulated with REDs -> zero the whole output
    cudaMemsetAsync(d_out, 0, (size_t)(OUT_ELEMS + LOUT_ELEMS) * sizeof(float), 0);

    lstm_kernel<<<HEADS * (BATCH / BC), NTHREADS>>>(
        x, Wih, Whh, bih, bhh, Wlin, blin, out, lout);
}

// round 17
// speedup vs baseline: 1.3961x; 1.3961x over previous
#include <cuda_runtime.h>

#define T_SEQ   2048
#define BATCH   64
#define INP     16
#define HEADS   8
#define HID     64
#define GATES   256
#define BC      2
#define NTHREADS 256
#define OUT_ELEMS  (T_SEQ * BATCH * HEADS)
#define LOUT_ELEMS (T_SEQ * BATCH * HID)

// Packed fp32x2 FMA (sm_100+): 2 MACs/instr, 2x FFMA throughput.
__device__ __forceinline__ float2 ffma2(float2 a, float2 b, float2 c) {
    float2 d;
    asm("fma.rn.f32x2 %0, %1, %2, %3;"
        : "=l"(reinterpret_cast<unsigned long long&>(d))
        : "l"(reinterpret_cast<const unsigned long long&>(a)),
          "l"(reinterpret_cast<const unsigned long long&>(b)),
          "l"(reinterpret_cast<const unsigned long long&>(c)));
    return d;
}

// Single-MUFU tanh (sm_75+). ~1e-5 abs err vs the 5-op EX2/RCP chain's 50 cy.
__device__ __forceinline__ float ftanh_(float x) {
    float r;
    asm("tanh.approx.f32 %0, %1;" : "=f"(r) : "f"(x));
    return r;
}
// sigmoid via tanh identity: 1 FMUL + 1 MUFU + 1 FMA (~25 cy chain).
__device__ __forceinline__ float fsig(float x) {
    return fmaf(0.5f, ftanh_(0.5f * x), 0.5f);
}

// CTA = (head, 2 batches), 256 threads, thread j = gate row j (both batches),
// occ 2. Phase 1: z + row-owned activation (tanh for g-rows, sigmoid else)
// -> zb. Phase 2: j<128 = (b,d) does the short c/h chain; j>=128 drains step
// t-1's lout/out via fire-and-forget REDs; threads 128..159 also run the x
// double-buffer pipeline (moved OFF the gate threads to shorten their tail).
__global__ void __launch_bounds__(NTHREADS, 2)
lstm_kernel(const float* __restrict__ x,    const float* __restrict__ Wih,
            const float* __restrict__ Whh,  const float* __restrict__ bih,
            const float* __restrict__ bhh,  const float* __restrict__ Wlin,
            const float* __restrict__ blin, float* __restrict__ out,
            float* __restrict__ lout)
{
    const int h    = blockIdx.x >> 5;          // head 0..7
    const int b0   = (blockIdx.x & 31) * BC;   // first batch of this CTA
    const int j    = threadIdx.x;              // gate row 0..255
    const int gate = j >> 6;                   // 0:i 1:f 2:g 3:o
    const int d    = j & (HID - 1);
    const int bb   = gate & 1;                 // phase-2 batch (j<128)

    __shared__ __align__(16) float hs[2][BC * HID];  // [buf][b*64+d]
    __shared__ __align__(16) float zb[BC][GATES];    // activated gates [b][row]
    __shared__ __align__(16) float xs[2][BC * INP];  // x double buffer

    // ---- weights -> registers (row j) ----
    float2 w2[HID / 2];
    {
        const float4* wr = reinterpret_cast<const float4*>(Whh + (size_t)(h * GATES + j) * HID);
#pragma unroll
        for (int q = 0; q < HID / 4; ++q) {
            float4 v = wr[q];
            w2[2 * q]     = make_float2(v.x, v.y);
            w2[2 * q + 1] = make_float2(v.z, v.w);
        }
    }
    float2 wi2[INP / 2];
    {
        const float4* wr = reinterpret_cast<const float4*>(Wih + (size_t)(h * GATES + j) * INP);
#pragma unroll
        for (int q = 0; q < INP / 4; ++q) {
            float4 v = wr[q];
            wi2[2 * q]     = make_float2(v.x, v.y);
            wi2[2 * q + 1] = make_float2(v.z, v.w);
        }
    }
    const float bias     = bih[h * GATES + j] + bhh[h * GATES + j];
    const float wlin_d   = Wlin[h * HID + d];
    const float blin_add = (d == 0) ? blin[h] : 0.0f;   // once per (t,b)

    // ---- init ----
    if (j < BC * HID) hs[0][j] = 0.0f;
    float c = 0.0f;
    float xreg = 0.0f;
    if (j >= 128 && j < 128 + BC * INP) {               // x pipeline threads
        const int xi = j - 128;
        xs[0][xi] = x[(size_t)0 * BATCH * INP + b0 * INP + xi];
        xreg      = x[(size_t)1 * BATCH * INP + b0 * INP + xi];
    }
    __syncthreads();

#pragma unroll 2
    for (int t = 0; t < T_SEQ; ++t) {
        // ---- phase 1: z_j[b] = bias + Whh_j.h[b] + Wih_j.x_t[b], then act ----
        const float* hb = hs[t & 1];
        const float* xb = xs[t & 1];
        float zr[BC];
#pragma unroll
        for (int b = 0; b < BC; ++b) {
            float2 a0 = make_float2(bias, 0.0f);
            float2 a1 = make_float2(0.0f, 0.0f);
            const float4* hv = reinterpret_cast<const float4*>(hb + b * HID);
#pragma unroll
            for (int q = 0; q < HID / 4; ++q) {
                float4 v = hv[q];
                a0 = ffma2(w2[2 * q],     make_float2(v.x, v.y), a0);
                a1 = ffma2(w2[2 * q + 1], make_float2(v.z, v.w), a1);
            }
            const float4* xv = reinterpret_cast<const float4*>(xb + b * INP);
#pragma unroll
            for (int q = 0; q < INP / 4; ++q) {
                float4 v = xv[q];
                a0 = ffma2(wi2[2 * q],     make_float2(v.x, v.y), a0);
                a1 = ffma2(wi2[2 * q + 1], make_float2(v.z, v.w), a1);
            }
            zr[b] = (a0.x + a0.y) + (a1.x + a1.y);
        }
        // row-owned nonlinearity (warp-uniform branch: warps 4-5 are g-rows)
        if (gate == 2) { zr[0] = ftanh_(zr[0]); zr[1] = ftanh_(zr[1]); }
        else           { zr[0] = fsig(zr[0]);   zr[1] = fsig(zr[1]);   }
        zb[0][j] = zr[0];
        zb[1][j] = zr[1];
        __syncthreads();

        // ---- phase 2 ----
        if (j < BC * HID) {
            // gate threads: short c/h chain only (single tanh.approx left)
            float si = zb[bb][0 * HID + d];
            float sf = zb[bb][1 * HID + d];
            float tg = zb[bb][2 * HID + d];
            float so = zb[bb][3 * HID + d];
            c = fmaf(sf, c, si * tg);
            hs[(t + 1) & 1][j] = so * ftanh_(c);   // j == bb*64+d here
        } else {
            if (t > 0) {
                // drain step t-1 outputs from hs[t&1] (h_{t-1}), fire-and-forget
                float hprev = hb[j - 128];         // (bb,d) = ((j>>6)&1, j&63)
                atomicAdd(lout + (size_t)((t - 1) * BATCH + b0 + bb) * HID + d, hprev);
                atomicAdd(out  + (size_t)((t - 1) * BATCH + b0 + bb) * HEADS + h,
                          fmaf(hprev, wlin_d, blin_add));
            }
            // x pipeline on drain-side threads 128..159
            if (j < 128 + BC * INP) {
                const int xi = j - 128;
                if (t + 1 < T_SEQ) xs[(t + 1) & 1][xi] = xreg;
                if (t + 2 < T_SEQ) xreg = x[(size_t)(t + 2) * BATCH * INP + b0 * INP + xi];
            }
        }
        __syncthreads();
    }

    // drain final step (t = T-1): h_{T-1} lives in hs[T_SEQ & 1] = hs[0]
    if (j >= BC * HID) {
        float hlast = hs[T_SEQ & 1][j - 128];
        atomicAdd(lout + (size_t)((T_SEQ - 1) * BATCH + b0 + bb) * HID + d, hlast);
        atomicAdd(out  + (size_t)((T_SEQ - 1) * BATCH + b0 + bb) * HEADS + h,
                  fmaf(hlast, wlin_d, blin_add));
    }
}

extern "C" void kernel_launch(void* const* d_in, const int* in_sizes, int n_in,
                              void* d_out, int out_size) {
    const float* x    = (const float*)d_in[0];
    const float* Wih  = (const float*)d_in[1];
    const float* Whh  = (const float*)d_in[2];
    const float* bih  = (const float*)d_in[3];
    const float* bhh  = (const float*)d_in[4];
    const float* Wlin = (const float*)d_in[5];
    const float* blin = (const float*)d_in[6];

    float* out  = (float*)d_out;                 // (T,B,H), atomic-accumulated
    float* lout = out + OUT_ELEMS;               // (T,B,HID), atomic-accumulated

    // both regions are accumulated with REDs -> zero the whole output
    cudaMemsetAsync(d_out, 0, (size_t)(OUT_ELEMS + LOUT_ELEMS) * sizeof(float), 0);

    lstm_kernel<<<HEADS * (BATCH / BC), NTHREADS>>>(
        x, Wih, Whh, bih, bhh, Wlin, blin, out, lout);
}